// round 3
// baseline (speedup 1.0000x reference)
#include <cuda_runtime.h>
#include <cstddef>

#define NN 50000
#define EE 1250000
#define HH 64
#define DD 128
#define GG 128
#define CC 10
#define LL 2

// ---------------- scratch (static __device__, no allocation) ----------------
__device__ __align__(16) float g_h[NN * HH];     // node features
__device__ __align__(16) float g_t[NN * HH];     // MLP intermediate
__device__ __align__(16) float g_h2[NN * HH];    // conv output pre-MLP
__device__ __align__(16) float g_agg[NN * HH];   // aggregated (pre-scaled) features
__device__ __align__(16) float g_pooled[GG * HH];

__device__ int g_degint[NN];
__device__ int g_off[NN + 1];
__device__ int g_cursor[NN];
__device__ int g_csr[EE];

// ---------------- zero degree histogram ----------------
__global__ void zero_deg_kernel() {
    int i = blockIdx.x * blockDim.x + threadIdx.x;
    if (i < NN) g_degint[i] = 0;
}

// ---------------- degree histogram over dst ----------------
__global__ void hist_kernel(const int* __restrict__ ei) {
    int e = blockIdx.x * blockDim.x + threadIdx.x;
    if (e < EE) atomicAdd(&g_degint[ei[EE + e]], 1);
}

// ---------------- exclusive scan (single block, 1024 threads) ----------------
__global__ void __launch_bounds__(1024) scan_kernel() {
    __shared__ int sm[1024];
    const int tid = threadIdx.x;
    const int CH = (NN + 1023) / 1024;   // 49
    const int base = tid * CH;

    int mysum = 0;
    for (int i = 0; i < CH; i++) {
        int idx = base + i;
        if (idx < NN) mysum += g_degint[idx];
    }
    sm[tid] = mysum;
    __syncthreads();
    // inclusive Hillis-Steele scan over 1024 partials
    for (int off = 1; off < 1024; off <<= 1) {
        int v = sm[tid];
        if (tid >= off) v += sm[tid - off];
        __syncthreads();
        sm[tid] = v;
        __syncthreads();
    }
    int run = sm[tid] - mysum;   // exclusive start for this chunk
    for (int i = 0; i < CH; i++) {
        int idx = base + i;
        if (idx < NN) {
            g_off[idx] = run;
            g_cursor[idx] = run;
            run += g_degint[idx];
        }
    }
    if (tid == 1023) g_off[NN] = sm[1023];
}

// ---------------- CSR fill ----------------
__global__ void fill_kernel(const int* __restrict__ ei) {
    int e = blockIdx.x * blockDim.x + threadIdx.x;
    if (e >= EE) return;
    int s = ei[e];
    int d = ei[EE + e];
    int pos = atomicAdd(&g_cursor[d], 1);
    g_csr[pos] = s;
}

// ---------------- aggregate: agg[n] = mean over incoming edges of h[src] ----
// one warp per node; lanes 0-15 = even edges, lanes 16-31 = odd edges,
// each lane owns one float4 column chunk (16 chunks x 4 = 64 cols)
__global__ void __launch_bounds__(256) agg_kernel() {
    int wid = (blockIdx.x * blockDim.x + threadIdx.x) >> 5;
    if (wid >= NN) return;
    int lane = threadIdx.x & 31;
    int half = lane >> 4;
    int l16 = lane & 15;

    int lo = g_off[wid];
    int hi = g_off[wid + 1];

    float4 acc = make_float4(0.f, 0.f, 0.f, 0.f);
    for (int e = lo + half; e < hi; e += 2) {
        int s = g_csr[e];
        float4 v = *(const float4*)(g_h + (size_t)s * HH + (l16 << 2));
        acc.x += v.x; acc.y += v.y; acc.z += v.z; acc.w += v.w;
    }
    // fold odd-edge half into even-edge half
    acc.x += __shfl_down_sync(0xffffffffu, acc.x, 16);
    acc.y += __shfl_down_sync(0xffffffffu, acc.y, 16);
    acc.z += __shfl_down_sync(0xffffffffu, acc.z, 16);
    acc.w += __shfl_down_sync(0xffffffffu, acc.w, 16);

    if (half == 0) {
        float inv = 1.0f / fmaxf((float)(hi - lo), 1.0f);
        acc.x *= inv; acc.y *= inv; acc.z *= inv; acc.w *= inv;
        *(float4*)(g_agg + (size_t)wid * HH + (l16 << 2)) = acc;
    }
}

// ---------------- generic fused GEMM ----------------
// out[N,64] = act( A1[N,K1] @ W1[K1,64] (+ A2[N,64] @ W2[64,64]) + bias )
// block: 64 rows x 64 cols, 256 threads, 4x4 microtile
__global__ void __launch_bounds__(256) gemm64_kernel(
    const float* __restrict__ A1, int K1,
    const float* __restrict__ W1,
    const float* __restrict__ A2,
    const float* __restrict__ W2,
    const float* __restrict__ bias,
    int do_relu,
    float* __restrict__ out)
{
    __shared__ float As[64][68];   // [row][k], padded (68*4 = 272 bytes, float4-safe)
    __shared__ float Ws[64][64];   // [k][col]

    const int tid = threadIdx.x;
    const int tx = tid & 15;       // col group
    const int ty = tid >> 4;       // row group
    const int row0 = blockIdx.x * 64;
    const int c0 = tx << 2;
    const int n0 = ty << 2;

    float acc[4][4];
#pragma unroll
    for (int i = 0; i < 4; i++)
#pragma unroll
        for (int j = 0; j < 4; j++) acc[i][j] = 0.f;

    const int nseg = (A2 != nullptr) ? 2 : 1;
    for (int s = 0; s < nseg; s++) {
        const float* A = (s == 0) ? A1 : A2;
        const float* W = (s == 0) ? W1 : W2;
        const int K = (s == 0) ? K1 : 64;
        const int kt_n = K >> 6;
        for (int kt = 0; kt < kt_n; kt++) {
            __syncthreads();
#pragma unroll
            for (int i = 0; i < 4; i++) {
                int idx = tid + i * 256;
                int n = idx >> 4;     // 0..63
                int kq = idx & 15;    // float4 index within 64-wide k tile
                int row = row0 + n;
                float4 v = make_float4(0.f, 0.f, 0.f, 0.f);
                if (row < NN)
                    v = *(const float4*)(A + (size_t)row * K + (kt << 6) + (kq << 2));
                *(float4*)&As[n][kq << 2] = v;
                *(float4*)&Ws[n][kq << 2] =
                    *(const float4*)(W + ((size_t)((kt << 6) + n)) * 64 + (kq << 2));
            }
            __syncthreads();
#pragma unroll
            for (int k4 = 0; k4 < 16; k4++) {
                float4 a[4], w[4];
#pragma unroll
                for (int i = 0; i < 4; i++)
                    a[i] = *(const float4*)&As[n0 + i][k4 << 2];
#pragma unroll
                for (int kk = 0; kk < 4; kk++)
                    w[kk] = *(const float4*)&Ws[(k4 << 2) + kk][c0];
#pragma unroll
                for (int i = 0; i < 4; i++) {
                    const float* ap = (const float*)&a[i];
#pragma unroll
                    for (int kk = 0; kk < 4; kk++) {
                        const float* wp = (const float*)&w[kk];
#pragma unroll
                        for (int j = 0; j < 4; j++)
                            acc[i][j] += ap[kk] * wp[j];
                    }
                }
            }
        }
    }

    float bv[4] = {0.f, 0.f, 0.f, 0.f};
    if (bias) {
        float4 b4 = *(const float4*)(bias + c0);
        bv[0] = b4.x; bv[1] = b4.y; bv[2] = b4.z; bv[3] = b4.w;
    }
#pragma unroll
    for (int i = 0; i < 4; i++) {
        int row = row0 + n0 + i;
        if (row < NN) {
            float4 o;
            o.x = acc[i][0] + bv[0];
            o.y = acc[i][1] + bv[1];
            o.z = acc[i][2] + bv[2];
            o.w = acc[i][3] + bv[3];
            if (do_relu) {
                o.x = fmaxf(o.x, 0.f); o.y = fmaxf(o.y, 0.f);
                o.z = fmaxf(o.z, 0.f); o.w = fmaxf(o.w, 0.f);
            }
            *(float4*)(out + (size_t)row * 64 + c0) = o;
        }
    }
}

// ---------------- mean pooling over sorted batch (no atomics) ----------------
__device__ __forceinline__ int lbound(const int* a, int n, int v) {
    int lo = 0, hi = n;
    while (lo < hi) {
        int m = (lo + hi) >> 1;
        if (a[m] < v) lo = m + 1; else hi = m;
    }
    return lo;
}

// one block per graph, 256 threads = 4 row-groups x 64 cols
__global__ void __launch_bounds__(256) pool_kernel(const int* __restrict__ batch) {
    __shared__ int s_lo, s_hi;
    __shared__ float sm[4][64];
    int g = blockIdx.x;
    int tid = threadIdx.x;
    if (tid == 0) {
        s_lo = lbound(batch, NN, g);
        s_hi = lbound(batch, NN, g + 1);
    }
    __syncthreads();
    int lo = s_lo, hi = s_hi;
    int col = tid & 63;
    int rg = tid >> 6;

    float acc = 0.f;
    for (int n = lo + rg; n < hi; n += 4)
        acc += g_h[(size_t)n * HH + col];
    sm[rg][col] = acc;
    __syncthreads();
    if (rg == 0) {
        float s = sm[0][col] + sm[1][col] + sm[2][col] + sm[3][col];
        float inv = 1.0f / fmaxf((float)(hi - lo), 1.0f);
        g_pooled[(size_t)g * HH + col] = s * inv;
    }
}

// ---------------- classifier ----------------
__global__ void cls_kernel(const float* __restrict__ W,
                           const float* __restrict__ b,
                           float* __restrict__ out)
{
    int tid = blockIdx.x * blockDim.x + threadIdx.x;
    if (tid >= GG * CC) return;
    int g = tid / CC;
    int c = tid % CC;
    float s = b[c];
#pragma unroll
    for (int k = 0; k < HH; k++)
        s += g_pooled[g * HH + k] * W[k * CC + c];
    out[tid] = s;
}

// ---------------- launcher ----------------
extern "C" void kernel_launch(void* const* d_in, const int* in_sizes, int n_in,
                              void* d_out, int out_size) {
    const float* x       = (const float*)d_in[0];
    const int*   ei      = (const int*)d_in[1];     // int32 (JAX x64 disabled)
    const int*   batch   = (const int*)d_in[2];     // int32
    const float* emb_w1  = (const float*)d_in[3];
    const float* emb_b1  = (const float*)d_in[4];
    const float* emb_w2  = (const float*)d_in[5];
    const float* emb_b2  = (const float*)d_in[6];
    const float* rel_w   = (const float*)d_in[7];
    const float* rel_b   = (const float*)d_in[8];
    const float* root_w  = (const float*)d_in[9];
    const float* post_w1 = (const float*)d_in[10];
    const float* post_b1 = (const float*)d_in[11];
    const float* post_w2 = (const float*)d_in[12];
    const float* post_b2 = (const float*)d_in[13];
    const float* cls_w   = (const float*)d_in[14];
    const float* cls_b   = (const float*)d_in[15];
    float*       out     = (float*)d_out;

    float *p_h, *p_t, *p_h2, *p_agg;
    cudaGetSymbolAddress((void**)&p_h, g_h);
    cudaGetSymbolAddress((void**)&p_t, g_t);
    cudaGetSymbolAddress((void**)&p_h2, g_h2);
    cudaGetSymbolAddress((void**)&p_agg, g_agg);

    const int TB = 256;
    const int gemm_blocks = (NN + 63) / 64;

    // ---- CSR build (once per launch) ----
    zero_deg_kernel<<<(NN + TB - 1) / TB, TB>>>();
    hist_kernel<<<(EE + TB - 1) / TB, TB>>>(ei);
    scan_kernel<<<1, 1024>>>();
    fill_kernel<<<(EE + TB - 1) / TB, TB>>>(ei);

    // ---- node embedding MLP: t = relu(x@W1+b1); h = t@W2+b2 ----
    gemm64_kernel<<<gemm_blocks, 256>>>(x, DD, emb_w1, nullptr, nullptr,
                                        emb_b1, 1, p_t);
    gemm64_kernel<<<gemm_blocks, 256>>>(p_t, HH, emb_w2, nullptr, nullptr,
                                        emb_b2, 0, p_h);

    for (int l = 0; l < LL; l++) {
        const float* rw  = rel_w   + (size_t)l * HH * HH;
        const float* rb  = rel_b   + (size_t)l * HH;
        const float* ow  = root_w  + (size_t)l * HH * HH;
        const float* pw1 = post_w1 + (size_t)l * HH * HH;
        const float* pb1 = post_b1 + (size_t)l * HH;
        const float* pw2 = post_w2 + (size_t)l * HH * HH;
        const float* pb2 = post_b2 + (size_t)l * HH;

        // agg = mean_{src->n} h[src]
        agg_kernel<<<(NN * 32 + TB - 1) / TB, TB>>>();

        // h2 = agg @ rel_w + rel_b + h @ root_w
        gemm64_kernel<<<gemm_blocks, 256>>>(p_agg, HH, rw, p_h, ow, rb, 0, p_h2);
        // t = relu(h2 @ post_w1 + post_b1)
        gemm64_kernel<<<gemm_blocks, 256>>>(p_h2, HH, pw1, nullptr, nullptr,
                                            pb1, 1, p_t);
        // h = relu(t @ post_w2 + post_b2)   (outer relu fused; relu∘relu = relu)
        gemm64_kernel<<<gemm_blocks, 256>>>(p_t, HH, pw2, nullptr, nullptr,
                                            pb2, 1, p_h);
    }

    // ---- mean pool (sorted batch) + classifier ----
    pool_kernel<<<GG, 256>>>(batch);
    cls_kernel<<<(GG * CC + TB - 1) / TB, TB>>>(cls_w, cls_b, out);
}

// round 4
// speedup vs baseline: 1.4331x; 1.4331x over previous
#include <cuda_runtime.h>
#include <cstddef>

#define NN 50000
#define EE 1250000
#define HH 64
#define DD 128
#define GG 128
#define CC 10
#define LL 2
#define NB 196   // (NN+255)/256

// ---------------- scratch (static __device__, no allocation) ----------------
__device__ __align__(16) float g_h[NN * HH];     // node features (updated in place)
__device__ __align__(16) float g_agg[NN * HH];   // aggregated mean features
__device__ __align__(16) float g_pooled[GG * HH];

__device__ int g_degint[NN];
__device__ int g_off[NN + 1];
__device__ int g_cursor[NN];
__device__ int g_bsum[NB];
__device__ int g_csr[EE];

// ---------------- CSR build ----------------
__global__ void zero_deg_kernel() {
    int i = blockIdx.x * blockDim.x + threadIdx.x;
    if (i < NN) g_degint[i] = 0;
}

__global__ void hist_kernel(const int* __restrict__ ei) {
    int e = blockIdx.x * blockDim.x + threadIdx.x;
    if (e < EE) atomicAdd(&g_degint[ei[EE + e]], 1);
}

// stage 1: per-block exclusive scan of 256 degrees, emit block totals
__global__ void __launch_bounds__(256) scan1_kernel() {
    __shared__ int sm[256];
    int t = threadIdx.x;
    int i = blockIdx.x * 256 + t;
    int v = (i < NN) ? g_degint[i] : 0;
    sm[t] = v;
    __syncthreads();
#pragma unroll
    for (int o = 1; o < 256; o <<= 1) {
        int x = sm[t];
        if (t >= o) x += sm[t - o];
        __syncthreads();
        sm[t] = x;
        __syncthreads();
    }
    if (i < NN) g_off[i] = sm[t] - v;          // local exclusive
    if (t == 255) g_bsum[blockIdx.x] = sm[255]; // block total
}

// stage 2: single block scans the 196 block totals (exclusive)
__global__ void __launch_bounds__(256) scan2_kernel() {
    __shared__ int sm[256];
    int t = threadIdx.x;
    int v = (t < NB) ? g_bsum[t] : 0;
    sm[t] = v;
    __syncthreads();
#pragma unroll
    for (int o = 1; o < 256; o <<= 1) {
        int x = sm[t];
        if (t >= o) x += sm[t - o];
        __syncthreads();
        sm[t] = x;
        __syncthreads();
    }
    if (t < NB) g_bsum[t] = sm[t] - v;
}

// stage 3: add block offsets, init cursor, set sentinel
__global__ void scan3_kernel() {
    int i = blockIdx.x * blockDim.x + threadIdx.x;
    if (i < NN) {
        int o = g_off[i] + g_bsum[i >> 8];
        g_off[i] = o;
        g_cursor[i] = o;
    }
    if (i == 0) g_off[NN] = EE;
}

__global__ void fill_kernel(const int* __restrict__ ei) {
    int e = blockIdx.x * blockDim.x + threadIdx.x;
    if (e >= EE) return;
    int s = ei[e];
    int d = ei[EE + e];
    int pos = atomicAdd(&g_cursor[d], 1);
    g_csr[pos] = s;
}

// ---------------- aggregate: agg[n] = mean over incoming edges of h[src] ----
__global__ void __launch_bounds__(256) agg_kernel() {
    int wid = (blockIdx.x * blockDim.x + threadIdx.x) >> 5;
    if (wid >= NN) return;
    int lane = threadIdx.x & 31;
    int half = lane >> 4;
    int l16 = lane & 15;

    int lo = g_off[wid];
    int hi = g_off[wid + 1];

    float4 acc = make_float4(0.f, 0.f, 0.f, 0.f);
    for (int e = lo + half; e < hi; e += 2) {
        int s = g_csr[e];
        float4 v = *(const float4*)(g_h + (size_t)s * HH + (l16 << 2));
        acc.x += v.x; acc.y += v.y; acc.z += v.z; acc.w += v.w;
    }
    acc.x += __shfl_down_sync(0xffffffffu, acc.x, 16);
    acc.y += __shfl_down_sync(0xffffffffu, acc.y, 16);
    acc.z += __shfl_down_sync(0xffffffffu, acc.z, 16);
    acc.w += __shfl_down_sync(0xffffffffu, acc.w, 16);

    if (half == 0) {
        float inv = 1.0f / fmaxf((float)(hi - lo), 1.0f);
        acc.x *= inv; acc.y *= inv; acc.z *= inv; acc.w *= inv;
        *(float4*)(g_agg + (size_t)wid * HH + (l16 << 2)) = acc;
    }
}

// ---------------- GEMM building blocks ----------------
// As: [64][68] staging, Ws: [64][64] (k-major), 256 threads, 4x4 microtile
__device__ __forceinline__ void mac64(const float* __restrict__ As,
                                      const float* __restrict__ Ws,
                                      float acc[4][4], int n0, int c0) {
#pragma unroll
    for (int k4 = 0; k4 < 16; k4++) {
        float4 a[4], w[4];
#pragma unroll
        for (int i = 0; i < 4; i++)
            a[i] = *(const float4*)(As + (n0 + i) * 68 + (k4 << 2));
#pragma unroll
        for (int kk = 0; kk < 4; kk++)
            w[kk] = *(const float4*)(Ws + ((k4 << 2) + kk) * 64 + c0);
#pragma unroll
        for (int i = 0; i < 4; i++) {
            const float* ap = (const float*)&a[i];
#pragma unroll
            for (int kk = 0; kk < 4; kk++) {
                const float* wp = (const float*)&w[kk];
#pragma unroll
                for (int j = 0; j < 4; j++)
                    acc[i][j] += ap[kk] * wp[j];
            }
        }
    }
}

// stage a 64-row x 64-col chunk of A[row0.., kofs..kofs+63] into As
__device__ __forceinline__ void stage_A(float* __restrict__ As,
                                        const float* __restrict__ A,
                                        int row0, int K, int kofs) {
    int tid = threadIdx.x;
#pragma unroll
    for (int i = 0; i < 4; i++) {
        int idx = tid + i * 256;
        int n = idx >> 4;
        int kq = idx & 15;
        int row = row0 + n;
        float4 v = make_float4(0.f, 0.f, 0.f, 0.f);
        if (row < NN)
            v = *(const float4*)(A + (size_t)row * K + kofs + (kq << 2));
        *(float4*)(As + n * 68 + (kq << 2)) = v;
    }
}

// write acc (rows n0..n0+3, cols c0..c0+3) into As
__device__ __forceinline__ void stage_acc(float* __restrict__ As,
                                          float acc[4][4], int n0, int c0) {
#pragma unroll
    for (int i = 0; i < 4; i++)
        *(float4*)(As + (n0 + i) * 68 + c0) =
            make_float4(acc[i][0], acc[i][1], acc[i][2], acc[i][3]);
}

__device__ __forceinline__ void zero_acc(float acc[4][4]) {
#pragma unroll
    for (int i = 0; i < 4; i++)
#pragma unroll
        for (int j = 0; j < 4; j++) acc[i][j] = 0.f;
}

// ---------------- fused embed MLP: h = relu(x@W1+b1)@W2 + b2 ----------------
__global__ void __launch_bounds__(256) embed_kernel(
    const float* __restrict__ x,
    const float* __restrict__ w1, const float* __restrict__ b1,
    const float* __restrict__ w2, const float* __restrict__ b2)
{
    extern __shared__ float sm[];
    float* W1s = sm;              // 128*64 = 8192
    float* W2s = sm + 8192;       // 64*64  = 4096
    float* As  = sm + 12288;      // 64*68  = 4352

    int tid = threadIdx.x;
#pragma unroll
    for (int i = 0; i < 8; i++) {
        int idx = (tid + i * 256) << 2;
        *(float4*)(W1s + idx) = *(const float4*)(w1 + idx);
    }
#pragma unroll
    for (int i = 0; i < 4; i++) {
        int idx = (tid + i * 256) << 2;
        *(float4*)(W2s + idx) = *(const float4*)(w2 + idx);
    }

    int row0 = blockIdx.x * 64;
    int tx = tid & 15, ty = tid >> 4;
    int c0 = tx << 2, n0 = ty << 2;

    float acc[4][4];
    zero_acc(acc);

    // GEMM1: x[.,128] @ W1, two 64-wide k chunks
    stage_A(As, x, row0, DD, 0);
    __syncthreads();            // covers weights + As
    mac64(As, W1s, acc, n0, c0);
    __syncthreads();
    stage_A(As, x, row0, DD, 64);
    __syncthreads();
    mac64(As, W1s + 64 * 64, acc, n0, c0);

    float4 b = *(const float4*)(b1 + c0);
    acc[0][0] += b.x; acc[0][1] += b.y; acc[0][2] += b.z; acc[0][3] += b.w;
    acc[1][0] += b.x; acc[1][1] += b.y; acc[1][2] += b.z; acc[1][3] += b.w;
    acc[2][0] += b.x; acc[2][1] += b.y; acc[2][2] += b.z; acc[2][3] += b.w;
    acc[3][0] += b.x; acc[3][1] += b.y; acc[3][2] += b.z; acc[3][3] += b.w;
#pragma unroll
    for (int i = 0; i < 4; i++)
#pragma unroll
        for (int j = 0; j < 4; j++) acc[i][j] = fmaxf(acc[i][j], 0.f);

    __syncthreads();
    stage_acc(As, acc, n0, c0);
    __syncthreads();

    // GEMM2: t @ W2 + b2 (no relu)
    zero_acc(acc);
    mac64(As, W2s, acc, n0, c0);
    b = *(const float4*)(b2 + c0);
#pragma unroll
    for (int i = 0; i < 4; i++) {
        int row = row0 + n0 + i;
        if (row < NN)
            *(float4*)(g_h + (size_t)row * 64 + c0) =
                make_float4(acc[i][0] + b.x, acc[i][1] + b.y,
                            acc[i][2] + b.z, acc[i][3] + b.w);
    }
}

// ---------------- fused conv layer ----------------
// h2 = agg@rel + h@root + rb ; t = relu(h2@pw1+pb1) ; h = relu(t@pw2+pb2)
__global__ void __launch_bounds__(256) layer_kernel(
    const float* __restrict__ rw, const float* __restrict__ rb,
    const float* __restrict__ ow,
    const float* __restrict__ pw1, const float* __restrict__ pb1,
    const float* __restrict__ pw2, const float* __restrict__ pb2)
{
    extern __shared__ float sm[];
    float* Wrel  = sm;            // 4096
    float* Wroot = sm + 4096;
    float* Wp1   = sm + 8192;
    float* Wp2   = sm + 12288;
    float* As    = sm + 16384;    // 64*68

    int tid = threadIdx.x;
#pragma unroll
    for (int i = 0; i < 4; i++) {
        int idx = (tid + i * 256) << 2;
        *(float4*)(Wrel  + idx) = *(const float4*)(rw  + idx);
        *(float4*)(Wroot + idx) = *(const float4*)(ow  + idx);
        *(float4*)(Wp1   + idx) = *(const float4*)(pw1 + idx);
        *(float4*)(Wp2   + idx) = *(const float4*)(pw2 + idx);
    }

    int row0 = blockIdx.x * 64;
    int tx = tid & 15, ty = tid >> 4;
    int c0 = tx << 2, n0 = ty << 2;

    float acc[4][4];
    zero_acc(acc);

    // h2 = agg@rel + h@root + rb
    stage_A(As, g_agg, row0, HH, 0);
    __syncthreads();            // weights + As visible
    mac64(As, Wrel, acc, n0, c0);
    __syncthreads();
    stage_A(As, g_h, row0, HH, 0);
    __syncthreads();
    mac64(As, Wroot, acc, n0, c0);

    float4 b = *(const float4*)(rb + c0);
#pragma unroll
    for (int i = 0; i < 4; i++) {
        acc[i][0] += b.x; acc[i][1] += b.y; acc[i][2] += b.z; acc[i][3] += b.w;
    }

    __syncthreads();
    stage_acc(As, acc, n0, c0);   // h2 -> As
    __syncthreads();

    // t = relu(h2@pw1 + pb1)
    zero_acc(acc);
    mac64(As, Wp1, acc, n0, c0);
    b = *(const float4*)(pb1 + c0);
#pragma unroll
    for (int i = 0; i < 4; i++) {
        acc[i][0] = fmaxf(acc[i][0] + b.x, 0.f);
        acc[i][1] = fmaxf(acc[i][1] + b.y, 0.f);
        acc[i][2] = fmaxf(acc[i][2] + b.z, 0.f);
        acc[i][3] = fmaxf(acc[i][3] + b.w, 0.f);
    }

    __syncthreads();
    stage_acc(As, acc, n0, c0);   // t -> As
    __syncthreads();

    // h = relu(t@pw2 + pb2)
    zero_acc(acc);
    mac64(As, Wp2, acc, n0, c0);
    b = *(const float4*)(pb2 + c0);
#pragma unroll
    for (int i = 0; i < 4; i++) {
        int row = row0 + n0 + i;
        if (row < NN)
            *(float4*)(g_h + (size_t)row * 64 + c0) =
                make_float4(fmaxf(acc[i][0] + b.x, 0.f),
                            fmaxf(acc[i][1] + b.y, 0.f),
                            fmaxf(acc[i][2] + b.z, 0.f),
                            fmaxf(acc[i][3] + b.w, 0.f));
    }
}

// ---------------- mean pooling over sorted batch (no atomics) ----------------
__device__ __forceinline__ int lbound(const int* a, int n, int v) {
    int lo = 0, hi = n;
    while (lo < hi) {
        int m = (lo + hi) >> 1;
        if (a[m] < v) lo = m + 1; else hi = m;
    }
    return lo;
}

__global__ void __launch_bounds__(256) pool_kernel(const int* __restrict__ batch) {
    __shared__ int s_lo, s_hi;
    __shared__ float sm[4][64];
    int g = blockIdx.x;
    int tid = threadIdx.x;
    if (tid == 0) {
        s_lo = lbound(batch, NN, g);
        s_hi = lbound(batch, NN, g + 1);
    }
    __syncthreads();
    int lo = s_lo, hi = s_hi;
    int col = tid & 63;
    int rg = tid >> 6;

    float acc = 0.f;
    for (int n = lo + rg; n < hi; n += 4)
        acc += g_h[(size_t)n * HH + col];
    sm[rg][col] = acc;
    __syncthreads();
    if (rg == 0) {
        float s = sm[0][col] + sm[1][col] + sm[2][col] + sm[3][col];
        float inv = 1.0f / fmaxf((float)(hi - lo), 1.0f);
        g_pooled[(size_t)g * HH + col] = s * inv;
    }
}

// ---------------- classifier ----------------
__global__ void cls_kernel(const float* __restrict__ W,
                           const float* __restrict__ b,
                           float* __restrict__ out)
{
    int tid = blockIdx.x * blockDim.x + threadIdx.x;
    if (tid >= GG * CC) return;
    int g = tid / CC;
    int c = tid % CC;
    float s = b[c];
#pragma unroll
    for (int k = 0; k < HH; k++)
        s += g_pooled[g * HH + k] * W[k * CC + c];
    out[tid] = s;
}

// ---------------- launcher ----------------
extern "C" void kernel_launch(void* const* d_in, const int* in_sizes, int n_in,
                              void* d_out, int out_size) {
    const float* x       = (const float*)d_in[0];
    const int*   ei      = (const int*)d_in[1];
    const int*   batch   = (const int*)d_in[2];
    const float* emb_w1  = (const float*)d_in[3];
    const float* emb_b1  = (const float*)d_in[4];
    const float* emb_w2  = (const float*)d_in[5];
    const float* emb_b2  = (const float*)d_in[6];
    const float* rel_w   = (const float*)d_in[7];
    const float* rel_b   = (const float*)d_in[8];
    const float* root_w  = (const float*)d_in[9];
    const float* post_w1 = (const float*)d_in[10];
    const float* post_b1 = (const float*)d_in[11];
    const float* post_w2 = (const float*)d_in[12];
    const float* post_b2 = (const float*)d_in[13];
    const float* cls_w   = (const float*)d_in[14];
    const float* cls_b   = (const float*)d_in[15];
    float*       out     = (float*)d_out;

    const int TB = 256;
    const int gemm_blocks = (NN + 63) / 64;   // 782

    const int embed_smem = (12288 + 64 * 68) * 4;   // 66,560 B
    const int layer_smem = (16384 + 64 * 68) * 4;   // 82,944 B
    cudaFuncSetAttribute(embed_kernel, cudaFuncAttributeMaxDynamicSharedMemorySize, embed_smem);
    cudaFuncSetAttribute(layer_kernel, cudaFuncAttributeMaxDynamicSharedMemorySize, layer_smem);

    // ---- CSR build ----
    zero_deg_kernel<<<(NN + TB - 1) / TB, TB>>>();
    hist_kernel<<<(EE + TB - 1) / TB, TB>>>(ei);
    scan1_kernel<<<NB, 256>>>();
    scan2_kernel<<<1, 256>>>();
    scan3_kernel<<<(NN + TB - 1) / TB, TB>>>();
    fill_kernel<<<(EE + TB - 1) / TB, TB>>>(ei);

    // ---- embed MLP ----
    embed_kernel<<<gemm_blocks, 256, embed_smem>>>(x, emb_w1, emb_b1, emb_w2, emb_b2);

    for (int l = 0; l < LL; l++) {
        agg_kernel<<<(NN * 32 + TB - 1) / TB, TB>>>();
        layer_kernel<<<gemm_blocks, 256, layer_smem>>>(
            rel_w   + (size_t)l * HH * HH,
            rel_b   + (size_t)l * HH,
            root_w  + (size_t)l * HH * HH,
            post_w1 + (size_t)l * HH * HH,
            post_b1 + (size_t)l * HH,
            post_w2 + (size_t)l * HH * HH,
            post_b2 + (size_t)l * HH);
    }

    // ---- mean pool + classifier ----
    pool_kernel<<<GG, 256>>>(batch);
    cls_kernel<<<(GG * CC + TB - 1) / TB, TB>>>(cls_w, cls_b, out);
}

// round 6
// speedup vs baseline: 1.7483x; 1.2199x over previous
#include <cuda_runtime.h>
#include <cuda_bf16.h>
#include <cstdint>
#include <cstddef>

#define NN 50000
#define EE 1250000
#define HH 64
#define DD 128
#define GG 128
#define CC 10
#define LL 2
#define NB 196            // (NN+255)/256
#define TILES64 782       // ceil(NN/64)
#define SA 72             // smem row stride in bf16 elements (conflict-free)

// ---------------- scratch (static __device__, no allocation) ----------------
__device__ __align__(16) float g_h[NN * HH];     // node features (in-place)
__device__ __align__(16) float g_agg[NN * HH];   // aggregated mean features
__device__ __align__(16) float g_pooled[GG * HH];

__device__ int g_degint[NN];
__device__ int g_off[NN + 1];
__device__ int g_cursor[NN];
__device__ int g_bsum[NB];
__device__ int g_csr[EE];

// ================= CSR build =================
__global__ void zero_deg_kernel() {
    int i = blockIdx.x * blockDim.x + threadIdx.x;
    if (i < NN) g_degint[i] = 0;
}
__global__ void hist_kernel(const int* __restrict__ ei) {
    int e = blockIdx.x * blockDim.x + threadIdx.x;
    if (e < EE) atomicAdd(&g_degint[ei[EE + e]], 1);
}
__global__ void __launch_bounds__(256) scan1_kernel() {
    __shared__ int sm[256];
    int t = threadIdx.x;
    int i = blockIdx.x * 256 + t;
    int v = (i < NN) ? g_degint[i] : 0;
    sm[t] = v;
    __syncthreads();
#pragma unroll
    for (int o = 1; o < 256; o <<= 1) {
        int x = sm[t];
        if (t >= o) x += sm[t - o];
        __syncthreads();
        sm[t] = x;
        __syncthreads();
    }
    if (i < NN) g_off[i] = sm[t] - v;
    if (t == 255) g_bsum[blockIdx.x] = sm[255];
}
__global__ void __launch_bounds__(256) scan2_kernel() {
    __shared__ int sm[256];
    int t = threadIdx.x;
    int v = (t < NB) ? g_bsum[t] : 0;
    sm[t] = v;
    __syncthreads();
#pragma unroll
    for (int o = 1; o < 256; o <<= 1) {
        int x = sm[t];
        if (t >= o) x += sm[t - o];
        __syncthreads();
        sm[t] = x;
        __syncthreads();
    }
    if (t < NB) g_bsum[t] = sm[t] - v;
}
__global__ void scan3_kernel() {
    int i = blockIdx.x * blockDim.x + threadIdx.x;
    if (i < NN) {
        int o = g_off[i] + g_bsum[i >> 8];
        g_off[i] = o;
        g_cursor[i] = o;
    }
    if (i == 0) g_off[NN] = EE;
}
__global__ void fill_kernel(const int* __restrict__ ei) {
    int e = blockIdx.x * blockDim.x + threadIdx.x;
    if (e >= EE) return;
    int s = ei[e];
    int d = ei[EE + e];
    int pos = atomicAdd(&g_cursor[d], 1);
    g_csr[pos] = s;
}

// ================= aggregation (LTS-bound) =================
__global__ void __launch_bounds__(256) agg_kernel() {
    int wid = (blockIdx.x * blockDim.x + threadIdx.x) >> 5;
    if (wid >= NN) return;
    int lane = threadIdx.x & 31;
    int half = lane >> 4;
    int l16 = lane & 15;

    int lo = g_off[wid];
    int hi = g_off[wid + 1];

    float4 acc = make_float4(0.f, 0.f, 0.f, 0.f);
    for (int e = lo + half; e < hi; e += 2) {
        int s = g_csr[e];
        float4 v = *(const float4*)(g_h + (size_t)s * HH + (l16 << 2));
        acc.x += v.x; acc.y += v.y; acc.z += v.z; acc.w += v.w;
    }
    acc.x += __shfl_down_sync(0xffffffffu, acc.x, 16);
    acc.y += __shfl_down_sync(0xffffffffu, acc.y, 16);
    acc.z += __shfl_down_sync(0xffffffffu, acc.z, 16);
    acc.w += __shfl_down_sync(0xffffffffu, acc.w, 16);

    if (half == 0) {
        float inv = 1.0f / fmaxf((float)(hi - lo), 1.0f);
        acc.x *= inv; acc.y *= inv; acc.z *= inv; acc.w *= inv;
        *(float4*)(g_agg + (size_t)wid * HH + (l16 << 2)) = acc;
    }
}

// ================= bf16 split + HMMA helpers =================
__device__ __forceinline__ void split2(float a, float b, uint32_t& hi, uint32_t& lo) {
    __nv_bfloat16 ha = __float2bfloat16(a), hb = __float2bfloat16(b);
    float ra = a - __bfloat162float(ha);
    float rb = b - __bfloat162float(hb);
    __nv_bfloat16 la = __float2bfloat16(ra), lb = __float2bfloat16(rb);
    hi = (uint32_t)__bfloat16_as_ushort(ha) | ((uint32_t)__bfloat16_as_ushort(hb) << 16);
    lo = (uint32_t)__bfloat16_as_ushort(la) | ((uint32_t)__bfloat16_as_ushort(lb) << 16);
}

__device__ __forceinline__ void mma_bf16(float* acc,
                                         uint32_t a0, uint32_t a1, uint32_t a2, uint32_t a3,
                                         uint32_t b0, uint32_t b1) {
    asm volatile(
        "mma.sync.aligned.m16n8k16.row.col.f32.bf16.bf16.f32 "
        "{%0,%1,%2,%3}, {%4,%5,%6,%7}, {%8,%9}, {%0,%1,%2,%3};"
        : "+f"(acc[0]), "+f"(acc[1]), "+f"(acc[2]), "+f"(acc[3])
        : "r"(a0), "r"(a1), "r"(a2), "r"(a3), "r"(b0), "r"(b1));
}

// SMEM byte offsets (dynamic smem base)
// A tiles: 64 x SA bf16 hi + lo
#define OFF_AHI 0
#define OFF_ALO (64 * SA * 2)                 // 9216
#define OFF_W   (2 * 64 * SA * 2)             // 18432; weight tiles 9216 B each
#define WT(i)   (OFF_W + (i) * 64 * SA * 2)

// stage A tile (64 rows x 64 cols) from fp32 global, split hi/lo bf16
__device__ __forceinline__ void stage_A(char* sm, const float* __restrict__ A,
                                        int row0, int K, int kofs) {
    int tid = threadIdx.x;
    int r = tid >> 2;                  // 0..63
    int c0 = (tid & 3) * 16;
    int row = row0 + r;
    float v[16];
    if (row < NN) {
        const float* src = A + (size_t)row * K + kofs + c0;
#pragma unroll
        for (int q = 0; q < 4; q++) {
            float4 f = *(const float4*)(src + q * 4);
            v[q * 4 + 0] = f.x; v[q * 4 + 1] = f.y;
            v[q * 4 + 2] = f.z; v[q * 4 + 3] = f.w;
        }
    } else {
#pragma unroll
        for (int q = 0; q < 16; q++) v[q] = 0.f;
    }
    uint32_t* hi = (uint32_t*)(sm + OFF_AHI + (size_t)(r * SA + c0) * 2);
    uint32_t* lo = (uint32_t*)(sm + OFF_ALO + (size_t)(r * SA + c0) * 2);
#pragma unroll
    for (int p = 0; p < 8; p++) {
        uint32_t h, l;
        split2(v[2 * p], v[2 * p + 1], h, l);
        hi[p] = h; lo[p] = l;
    }
}

// stage weight tile pair: Wt[n][k] (bf16 hi/lo) from W[kbase+k][n] fp32
__device__ __forceinline__ void stage_W(char* sm, int hi_off, int lo_off,
                                        const float* __restrict__ W, int kbase) {
    int tid = threadIdx.x;
    int n = tid >> 2;                  // 0..63
    int kc = (tid & 3) * 16;
    uint32_t* hi = (uint32_t*)(sm + hi_off + (size_t)(n * SA + kc) * 2);
    uint32_t* lo = (uint32_t*)(sm + lo_off + (size_t)(n * SA + kc) * 2);
#pragma unroll
    for (int p = 0; p < 8; p++) {
        int k = kc + 2 * p;
        float a = W[(size_t)(kbase + k) * 64 + n];
        float b = W[(size_t)(kbase + k + 1) * 64 + n];
        uint32_t h, l;
        split2(a, b, h, l);
        hi[p] = h; lo[p] = l;
    }
}

// one split GEMM unit over K = ksteps*16: acc += A(64xK) @ W(Kx64) (warp's 16x32 slice)
__device__ __forceinline__ void gemm_unit(const char* sm, int wHi, int wLo,
                                          float acc[16], int ksteps) {
    int lane = threadIdx.x & 31;
    int wid = threadIdx.x >> 5;
    int mt = (wid & 3) * 16;
    int nb = (wid >> 2) * 32;
    int g = lane >> 2, tg = lane & 3;
    int r0 = (mt + g) * SA;
    int r1 = (mt + g + 8) * SA;

    for (int ks = 0; ks < ksteps; ks++) {
        int kb = ks * 16 + tg * 2;
        uint32_t ah0 = *(const uint32_t*)(sm + OFF_AHI + (size_t)(r0 + kb) * 2);
        uint32_t ah1 = *(const uint32_t*)(sm + OFF_AHI + (size_t)(r1 + kb) * 2);
        uint32_t ah2 = *(const uint32_t*)(sm + OFF_AHI + (size_t)(r0 + kb + 8) * 2);
        uint32_t ah3 = *(const uint32_t*)(sm + OFF_AHI + (size_t)(r1 + kb + 8) * 2);
        uint32_t al0 = *(const uint32_t*)(sm + OFF_ALO + (size_t)(r0 + kb) * 2);
        uint32_t al1 = *(const uint32_t*)(sm + OFF_ALO + (size_t)(r1 + kb) * 2);
        uint32_t al2 = *(const uint32_t*)(sm + OFF_ALO + (size_t)(r0 + kb + 8) * 2);
        uint32_t al3 = *(const uint32_t*)(sm + OFF_ALO + (size_t)(r1 + kb + 8) * 2);
#pragma unroll
        for (int j = 0; j < 4; j++) {
            int nrow = (nb + j * 8 + g) * SA;
            uint32_t bh0 = *(const uint32_t*)(sm + wHi + (size_t)(nrow + kb) * 2);
            uint32_t bh1 = *(const uint32_t*)(sm + wHi + (size_t)(nrow + kb + 8) * 2);
            uint32_t bl0 = *(const uint32_t*)(sm + wLo + (size_t)(nrow + kb) * 2);
            uint32_t bl1 = *(const uint32_t*)(sm + wLo + (size_t)(nrow + kb + 8) * 2);
            mma_bf16(acc + j * 4, ah0, ah1, ah2, ah3, bh0, bh1);
            mma_bf16(acc + j * 4, ah0, ah1, ah2, ah3, bl0, bl1);
            mma_bf16(acc + j * 4, al0, al1, al2, al3, bh0, bh1);
        }
    }
}

__device__ __forceinline__ void zero16(float* a) {
#pragma unroll
    for (int i = 0; i < 16; i++) a[i] = 0.f;
}

// epilogue: acc + bias (opt relu) -> re-split into A tile in SMEM
__device__ __forceinline__ void epi_to_A(char* sm, const float acc[16],
                                         const float* __restrict__ bias, bool relu) {
    int lane = threadIdx.x & 31;
    int wid = threadIdx.x >> 5;
    int mt = (wid & 3) * 16;
    int nb = (wid >> 2) * 32;
    int g = lane >> 2, tg = lane & 3;
    int r0 = (mt + g) * SA;
    int r1 = (mt + g + 8) * SA;
#pragma unroll
    for (int j = 0; j < 4; j++) {
        int col = nb + j * 8 + tg * 2;
        float b0 = __ldg(bias + col), b1 = __ldg(bias + col + 1);
        float v00 = acc[j * 4 + 0] + b0, v01 = acc[j * 4 + 1] + b1;
        float v10 = acc[j * 4 + 2] + b0, v11 = acc[j * 4 + 3] + b1;
        if (relu) {
            v00 = fmaxf(v00, 0.f); v01 = fmaxf(v01, 0.f);
            v10 = fmaxf(v10, 0.f); v11 = fmaxf(v11, 0.f);
        }
        uint32_t h, l;
        split2(v00, v01, h, l);
        *(uint32_t*)(sm + OFF_AHI + (size_t)(r0 + col) * 2) = h;
        *(uint32_t*)(sm + OFF_ALO + (size_t)(r0 + col) * 2) = l;
        split2(v10, v11, h, l);
        *(uint32_t*)(sm + OFF_AHI + (size_t)(r1 + col) * 2) = h;
        *(uint32_t*)(sm + OFF_ALO + (size_t)(r1 + col) * 2) = l;
    }
}

// final epilogue: acc + bias (opt relu) -> fp32 g_h
__device__ __forceinline__ void epi_to_gmem(const float acc[16],
                                            const float* __restrict__ bias,
                                            bool relu, int row0) {
    int lane = threadIdx.x & 31;
    int wid = threadIdx.x >> 5;
    int mt = (wid & 3) * 16;
    int nb = (wid >> 2) * 32;
    int g = lane >> 2, tg = lane & 3;
    int ra = row0 + mt + g;
    int rb = ra + 8;
#pragma unroll
    for (int j = 0; j < 4; j++) {
        int col = nb + j * 8 + tg * 2;
        float b0 = __ldg(bias + col), b1 = __ldg(bias + col + 1);
        float v00 = acc[j * 4 + 0] + b0, v01 = acc[j * 4 + 1] + b1;
        float v10 = acc[j * 4 + 2] + b0, v11 = acc[j * 4 + 3] + b1;
        if (relu) {
            v00 = fmaxf(v00, 0.f); v01 = fmaxf(v01, 0.f);
            v10 = fmaxf(v10, 0.f); v11 = fmaxf(v11, 0.f);
        }
        if (ra < NN) *(float2*)(g_h + (size_t)ra * 64 + col) = make_float2(v00, v01);
        if (rb < NN) *(float2*)(g_h + (size_t)rb * 64 + col) = make_float2(v10, v11);
    }
}

// ================= fused embed MLP: h = relu(x@W1+b1)@W2 + b2 =================
__global__ void __launch_bounds__(256) embed_kernel(
    const float* __restrict__ x,
    const float* __restrict__ w1, const float* __restrict__ b1,
    const float* __restrict__ w2, const float* __restrict__ b2)
{
    extern __shared__ char sm[];
    int row0 = blockIdx.x * 64;

    // tiles: 0=w1a_hi 1=w1a_lo 2=w1b_hi 3=w1b_lo 4=w2_hi 5=w2_lo
    stage_W(sm, WT(0), WT(1), w1, 0);
    stage_W(sm, WT(2), WT(3), w1, 64);
    stage_W(sm, WT(4), WT(5), w2, 0);
    stage_A(sm, x, row0, DD, 0);
    __syncthreads();

    float acc[16];
    zero16(acc);
    gemm_unit(sm, WT(0), WT(1), acc, 4);    // x[:,0:64] @ W1[0:64]
    __syncthreads();
    stage_A(sm, x, row0, DD, 64);
    __syncthreads();
    gemm_unit(sm, WT(2), WT(3), acc, 4);    // += x[:,64:128] @ W1[64:128]
    __syncthreads();
    epi_to_A(sm, acc, b1, true);            // t = relu(.+b1)
    __syncthreads();

    zero16(acc);
    gemm_unit(sm, WT(4), WT(5), acc, 4);    // t @ W2
    epi_to_gmem(acc, b2, false, row0);      // h = . + b2
}

// ================= fused conv layer =================
// h2 = agg@rel + h@root + rb ; t = relu(h2@pw1+pb1) ; h = relu(t@pw2+pb2)
__global__ void __launch_bounds__(256) layer_kernel(
    const float* __restrict__ rw, const float* __restrict__ rb,
    const float* __restrict__ ow,
    const float* __restrict__ pw1, const float* __restrict__ pb1,
    const float* __restrict__ pw2, const float* __restrict__ pb2)
{
    extern __shared__ char sm[];
    int row0 = blockIdx.x * 64;

    // tiles: 0=rel_hi 1=rel_lo 2=root_hi 3=root_lo 4=p1_hi 5=p1_lo 6=p2_hi 7=p2_lo
    stage_W(sm, WT(0), WT(1), rw, 0);
    stage_W(sm, WT(2), WT(3), ow, 0);
    stage_W(sm, WT(4), WT(5), pw1, 0);
    stage_W(sm, WT(6), WT(7), pw2, 0);
    stage_A(sm, g_agg, row0, HH, 0);
    __syncthreads();

    float acc[16];
    zero16(acc);
    gemm_unit(sm, WT(0), WT(1), acc, 4);    // agg @ rel
    __syncthreads();
    stage_A(sm, g_h, row0, HH, 0);
    __syncthreads();
    gemm_unit(sm, WT(2), WT(3), acc, 4);    // += h @ root
    __syncthreads();
    epi_to_A(sm, acc, rb, false);           // h2 = . + rb
    __syncthreads();

    zero16(acc);
    gemm_unit(sm, WT(4), WT(5), acc, 4);    // h2 @ pw1
    __syncthreads();
    epi_to_A(sm, acc, pb1, true);           // t = relu(.+pb1)
    __syncthreads();

    zero16(acc);
    gemm_unit(sm, WT(6), WT(7), acc, 4);    // t @ pw2
    epi_to_gmem(acc, pb2, true, row0);      // h = relu(.+pb2)
}

// ================= pooling + classifier =================
__device__ __forceinline__ int lbound(const int* a, int n, int v) {
    int lo = 0, hi = n;
    while (lo < hi) {
        int m = (lo + hi) >> 1;
        if (a[m] < v) lo = m + 1; else hi = m;
    }
    return lo;
}

__global__ void __launch_bounds__(256) pool_kernel(const int* __restrict__ batch) {
    __shared__ int s_lo, s_hi;
    __shared__ float sm[4][64];
    int g = blockIdx.x;
    int tid = threadIdx.x;
    if (tid == 0) {
        s_lo = lbound(batch, NN, g);
        s_hi = lbound(batch, NN, g + 1);
    }
    __syncthreads();
    int lo = s_lo, hi = s_hi;
    int col = tid & 63;
    int rg = tid >> 6;

    float acc = 0.f;
    for (int n = lo + rg; n < hi; n += 4)
        acc += g_h[(size_t)n * HH + col];
    sm[rg][col] = acc;
    __syncthreads();
    if (rg == 0) {
        float s = sm[0][col] + sm[1][col] + sm[2][col] + sm[3][col];
        float inv = 1.0f / fmaxf((float)(hi - lo), 1.0f);
        g_pooled[(size_t)g * HH + col] = s * inv;
    }
}

__global__ void cls_kernel(const float* __restrict__ W,
                           const float* __restrict__ b,
                           float* __restrict__ out)
{
    int tid = blockIdx.x * blockDim.x + threadIdx.x;
    if (tid >= GG * CC) return;
    int g = tid / CC;
    int c = tid % CC;
    float s = b[c];
#pragma unroll
    for (int k = 0; k < HH; k++)
        s += g_pooled[g * HH + k] * W[k * CC + c];
    out[tid] = s;
}

// ================= launcher =================
extern "C" void kernel_launch(void* const* d_in, const int* in_sizes, int n_in,
                              void* d_out, int out_size) {
    const float* x       = (const float*)d_in[0];
    const int*   ei      = (const int*)d_in[1];
    const int*   batch   = (const int*)d_in[2];
    const float* emb_w1  = (const float*)d_in[3];
    const float* emb_b1  = (const float*)d_in[4];
    const float* emb_w2  = (const float*)d_in[5];
    const float* emb_b2  = (const float*)d_in[6];
    const float* rel_w   = (const float*)d_in[7];
    const float* rel_b   = (const float*)d_in[8];
    const float* root_w  = (const float*)d_in[9];
    const float* post_w1 = (const float*)d_in[10];
    const float* post_b1 = (const float*)d_in[11];
    const float* post_w2 = (const float*)d_in[12];
    const float* post_b2 = (const float*)d_in[13];
    const float* cls_w   = (const float*)d_in[14];
    const float* cls_b   = (const float*)d_in[15];
    float*       out     = (float*)d_out;

    const int TB = 256;
    const int tile_bytes = 64 * SA * 2;          // 9216
    const int embed_smem = OFF_W + 6 * tile_bytes;   // 73,728 B
    const int layer_smem = OFF_W + 8 * tile_bytes;   // 92,160 B
    cudaFuncSetAttribute(embed_kernel, cudaFuncAttributeMaxDynamicSharedMemorySize, embed_smem);
    cudaFuncSetAttribute(layer_kernel, cudaFuncAttributeMaxDynamicSharedMemorySize, layer_smem);

    // ---- CSR build ----
    zero_deg_kernel<<<(NN + TB - 1) / TB, TB>>>();
    hist_kernel<<<(EE + TB - 1) / TB, TB>>>(ei);
    scan1_kernel<<<NB, 256>>>();
    scan2_kernel<<<1, 256>>>();
    scan3_kernel<<<(NN + TB - 1) / TB, TB>>>();
    fill_kernel<<<(EE + TB - 1) / TB, TB>>>(ei);

    // ---- embed MLP ----
    embed_kernel<<<TILES64, 256, embed_smem>>>(x, emb_w1, emb_b1, emb_w2, emb_b2);

    for (int l = 0; l < LL; l++) {
        agg_kernel<<<(NN * 32 + TB - 1) / TB, TB>>>();
        layer_kernel<<<TILES64, 256, layer_smem>>>(
            rel_w   + (size_t)l * HH * HH,
            rel_b   + (size_t)l * HH,
            root_w  + (size_t)l * HH * HH,
            post_w1 + (size_t)l * HH * HH,
            post_b1 + (size_t)l * HH,
            post_w2 + (size_t)l * HH * HH,
            post_b2 + (size_t)l * HH);
    }

    // ---- mean pool + classifier ----
    pool_kernel<<<GG, 256>>>(batch);
    cls_kernel<<<(GG * CC + TB - 1) / TB, TB>>>(cls_w, cls_b, out);
}